// round 16
// baseline (speedup 1.0000x reference)
#include <cuda_runtime.h>

// DenselyCnnAttLayer — FINAL CONVERGED KERNEL (R9 structure).
// out[b,s,d] = sum_l softmax_m( sum_l' s[b,s,l'] * Ws[s,l',m] )[l] * x_l[b,s,d]
// where s[b,s,l] = sum_d x_l[b,s,d].  B=64, S=512, L=6, D=512, fp32.
//
// One warp == one CTA == one (b,s) row. 24 front-batched streaming LDG.128
// into registers, shuffle-tree warp reduction, redundant per-lane 6x6
// projection + softmax, 4 coalesced streaming STG.128. Grid 32768 x 32.
//
// Session record (15 measured rounds):
//   best harness 69.73us / best ncu 65.92us / best DRAM 85.4% (6.77TB/s).
//   Rejected by measurement: block-per-row+barrier (83.5%), smem staging
//   (72.5%), persistent grid-stride (78.7%), TMA 2-slot ring (77.9%),
//   L2-prefetch double-row (72.6%), redux.f32 (absent on sm_103),
//   L2::256B hint (83.3%), LDG.256/STG.256 (ncu +1.5us), 4-warp CTAs
//   (84.7-85.0%). Re-lands of this structure span 69.7-70.4us = noise.
// Physics: traffic provably minimal (470MB, each element touched once;
// ncu_time x achieved_BW == 470MB); DRAM% insensitive to occupancy,
// scheduling, request width, hints -> pinned at the HBM3e mixed-stream
// ceiling (~85% of 8TB/s spec). Nothing kernel-side remains.

#define DD    512
#define LL    6
#define CHNK  4            // float4 chunks per lane per layer (512/32/4)
#define NTHR  32           // ONE warp per CTA

__global__ __launch_bounds__(NTHR)
void dense_att_kernel(const float* __restrict__ x0,
                      const float* __restrict__ x1,
                      const float* __restrict__ x2,
                      const float* __restrict__ x3,
                      const float* __restrict__ x4,
                      const float* __restrict__ x5,
                      const float* __restrict__ Ws,   // [S, L, L]
                      float* __restrict__ out)        // [B, S, D]
{
    const int lane = threadIdx.x;
    const int row  = blockIdx.x;             // b*S + s
    const int s    = row & 511;              // S = 512

    // lane handles float4s at d = c*128 + lane*4, c = 0..3 (coalesced)
    const size_t base = (size_t)row * DD + (size_t)lane * 4;

    const float* xs[LL] = {x0, x1, x2, x3, x4, x5};

    // 24 front-batched streaming LDG.128 (each element touched exactly once).
    float4 v[LL][CHNK];
#pragma unroll
    for (int j = 0; j < LL; j++) {
#pragma unroll
        for (int c = 0; c < CHNK; c++) {
            v[j][c] = __ldcs(reinterpret_cast<const float4*>(xs[j] + base + c * 128));
        }
    }

    float p[LL];
#pragma unroll
    for (int j = 0; j < LL; j++) {
        float a0 = (v[j][0].x + v[j][0].y) + (v[j][0].z + v[j][0].w);
        float a1 = (v[j][1].x + v[j][1].y) + (v[j][1].z + v[j][1].w);
        float a2 = (v[j][2].x + v[j][2].y) + (v[j][2].z + v[j][2].w);
        float a3 = (v[j][3].x + v[j][3].y) + (v[j][3].z + v[j][3].w);
        p[j] = (a0 + a1) + (a2 + a3);
    }

    // Warp butterfly: all lanes end with the full per-layer sums.
    // (redux.sync.add is integer-only on sm_103 — shuffle tree required.)
#pragma unroll
    for (int off = 16; off > 0; off >>= 1) {
#pragma unroll
        for (int j = 0; j < LL; j++) {
            p[j] += __shfl_xor_sync(0xffffffffu, p[j], off);
        }
    }

    // Redundant per-lane 6x6 projection + softmax (warp-uniform Ws loads;
    // Ws is 73KB total, L2/L1 hot).
    const float* W = Ws + (size_t)s * (LL * LL);
    float logit[LL];
#pragma unroll
    for (int m = 0; m < LL; m++) logit[m] = 0.0f;
#pragma unroll
    for (int l = 0; l < LL; l++) {
        const float sl = p[l];
#pragma unroll
        for (int m = 0; m < LL; m++) {
            logit[m] = fmaf(sl, __ldg(W + l * LL + m), logit[m]);
        }
    }

    float mx = logit[0];
#pragma unroll
    for (int m = 1; m < LL; m++) mx = fmaxf(mx, logit[m]);
    float a[LL];
    float den = 0.0f;
#pragma unroll
    for (int m = 0; m < LL; m++) {
        a[m] = __expf(logit[m] - mx);
        den += a[m];
    }
    const float inv = __frcp_rn(den);
#pragma unroll
    for (int m = 0; m < LL; m++) a[m] *= inv;

    // Weighted combine over layers, 4 coalesced streaming stores.
#pragma unroll
    for (int c = 0; c < CHNK; c++) {
        float4 o;
        o.x = o.y = o.z = o.w = 0.0f;
#pragma unroll
        for (int j = 0; j < LL; j++) {
            o.x = fmaf(a[j], v[j][c].x, o.x);
            o.y = fmaf(a[j], v[j][c].y, o.y);
            o.z = fmaf(a[j], v[j][c].z, o.z);
            o.w = fmaf(a[j], v[j][c].w, o.w);
        }
        __stcs(reinterpret_cast<float4*>(out + base + c * 128), o);
    }
}

extern "C" void kernel_launch(void* const* d_in, const int* in_sizes, int n_in,
                              void* d_out, int out_size)
{
    const float* x0 = (const float*)d_in[0];
    const float* x1 = (const float*)d_in[1];
    const float* x2 = (const float*)d_in[2];
    const float* x3 = (const float*)d_in[3];
    const float* x4 = (const float*)d_in[4];
    const float* x5 = (const float*)d_in[5];
    const float* Ws = (const float*)d_in[6];
    float* out = (float*)d_out;

    const int rows = in_sizes[0] / DD;          // B*S = 32768
    dense_att_kernel<<<rows, NTHR>>>(x0, x1, x2, x3, x4, x5, Ws, out);
}

// round 17
// speedup vs baseline: 1.0037x; 1.0037x over previous
#include <cuda_runtime.h>

// DenselyCnnAttLayer — FINAL CONVERGED KERNEL (R9 structure).
// out[b,s,d] = sum_l softmax_m( sum_l' s[b,s,l'] * Ws[s,l',m] )[l] * x_l[b,s,d]
// where s[b,s,l] = sum_d x_l[b,s,d].  B=64, S=512, L=6, D=512, fp32.
//
// One warp == one CTA == one (b,s) row. 24 front-batched streaming LDG.128
// into registers, shuffle-tree warp reduction, redundant per-lane 6x6
// projection + softmax, 4 coalesced streaming STG.128. Grid 32768 x 32.
//
// Session record (16 measured rounds):
//   best harness 69.73us / best ncu 65.92us / best DRAM 85.4% (6.77TB/s).
//   Champion re-land band: harness 69.73-70.40us, ncu 65.92-66.30us.
//   Rejected by measurement: block-per-row+barrier (83.5%), smem staging
//   (72.5%), persistent grid-stride (78.7%), TMA 2-slot ring (77.9%),
//   L2-prefetch double-row (72.6%), redux.f32 (absent on sm_103),
//   L2::256B hint (83.3%), LDG.256/STG.256 (ncu +1.5us), 4-warp CTAs
//   (84.7-85.0%).
// Physics: traffic provably minimal (470MB, each element touched once);
// best ncu time == 470MB / 6.78TB/s exactly -> the kernel runs at its
// traffic minimum times the achievable mixed-stream HBM3e bandwidth
// (~85% of 8TB/s spec, path-independent LTS cap). Converged.

#define DD    512
#define LL    6
#define CHNK  4            // float4 chunks per lane per layer (512/32/4)
#define NTHR  32           // ONE warp per CTA

__global__ __launch_bounds__(NTHR)
void dense_att_kernel(const float* __restrict__ x0,
                      const float* __restrict__ x1,
                      const float* __restrict__ x2,
                      const float* __restrict__ x3,
                      const float* __restrict__ x4,
                      const float* __restrict__ x5,
                      const float* __restrict__ Ws,   // [S, L, L]
                      float* __restrict__ out)        // [B, S, D]
{
    const int lane = threadIdx.x;
    const int row  = blockIdx.x;             // b*S + s
    const int s    = row & 511;              // S = 512

    // lane handles float4s at d = c*128 + lane*4, c = 0..3 (coalesced)
    const size_t base = (size_t)row * DD + (size_t)lane * 4;

    const float* xs[LL] = {x0, x1, x2, x3, x4, x5};

    // 24 front-batched streaming LDG.128 (each element touched exactly once).
    float4 v[LL][CHNK];
#pragma unroll
    for (int j = 0; j < LL; j++) {
#pragma unroll
        for (int c = 0; c < CHNK; c++) {
            v[j][c] = __ldcs(reinterpret_cast<const float4*>(xs[j] + base + c * 128));
        }
    }

    float p[LL];
#pragma unroll
    for (int j = 0; j < LL; j++) {
        float a0 = (v[j][0].x + v[j][0].y) + (v[j][0].z + v[j][0].w);
        float a1 = (v[j][1].x + v[j][1].y) + (v[j][1].z + v[j][1].w);
        float a2 = (v[j][2].x + v[j][2].y) + (v[j][2].z + v[j][2].w);
        float a3 = (v[j][3].x + v[j][3].y) + (v[j][3].z + v[j][3].w);
        p[j] = (a0 + a1) + (a2 + a3);
    }

    // Warp butterfly: all lanes end with the full per-layer sums.
    // (redux.sync.add is integer-only on sm_103 — shuffle tree required.)
#pragma unroll
    for (int off = 16; off > 0; off >>= 1) {
#pragma unroll
        for (int j = 0; j < LL; j++) {
            p[j] += __shfl_xor_sync(0xffffffffu, p[j], off);
        }
    }

    // Redundant per-lane 6x6 projection + softmax (warp-uniform Ws loads;
    // Ws is 73KB total, L2/L1 hot).
    const float* W = Ws + (size_t)s * (LL * LL);
    float logit[LL];
#pragma unroll
    for (int m = 0; m < LL; m++) logit[m] = 0.0f;
#pragma unroll
    for (int l = 0; l < LL; l++) {
        const float sl = p[l];
#pragma unroll
        for (int m = 0; m < LL; m++) {
            logit[m] = fmaf(sl, __ldg(W + l * LL + m), logit[m]);
        }
    }

    float mx = logit[0];
#pragma unroll
    for (int m = 1; m < LL; m++) mx = fmaxf(mx, logit[m]);
    float a[LL];
    float den = 0.0f;
#pragma unroll
    for (int m = 0; m < LL; m++) {
        a[m] = __expf(logit[m] - mx);
        den += a[m];
    }
    const float inv = __frcp_rn(den);
#pragma unroll
    for (int m = 0; m < LL; m++) a[m] *= inv;

    // Weighted combine over layers, 4 coalesced streaming stores.
#pragma unroll
    for (int c = 0; c < CHNK; c++) {
        float4 o;
        o.x = o.y = o.z = o.w = 0.0f;
#pragma unroll
        for (int j = 0; j < LL; j++) {
            o.x = fmaf(a[j], v[j][c].x, o.x);
            o.y = fmaf(a[j], v[j][c].y, o.y);
            o.z = fmaf(a[j], v[j][c].z, o.z);
            o.w = fmaf(a[j], v[j][c].w, o.w);
        }
        __stcs(reinterpret_cast<float4*>(out + base + c * 128), o);
    }
}

extern "C" void kernel_launch(void* const* d_in, const int* in_sizes, int n_in,
                              void* d_out, int out_size)
{
    const float* x0 = (const float*)d_in[0];
    const float* x1 = (const float*)d_in[1];
    const float* x2 = (const float*)d_in[2];
    const float* x3 = (const float*)d_in[3];
    const float* x4 = (const float*)d_in[4];
    const float* x5 = (const float*)d_in[5];
    const float* Ws = (const float*)d_in[6];
    float* out = (float*)d_out;

    const int rows = in_sizes[0] / DD;          // B*S = 32768
    dense_att_kernel<<<rows, NTHR>>>(x0, x1, x2, x3, x4, x5, Ws, out);
}